// round 16
// baseline (speedup 1.0000x reference)
#include <cuda_runtime.h>
#include <cuda_fp16.h>
#include <math.h>

#define NN 100000
#define NE 3200000
#define DF 128
#define HID 16
#define NC 2
#define GB 256              // nodes (and threads) per gemm block
#define XP 33               // XS row stride (odd): conflict-free
#define KC 32               // k-chunk size
#define GEMM_BLKS 391       // ceil(NN/GB) per k-half
#define DEG_BLKS 205
#define FUSED_BLKS (2 * GEMM_BLKS + DEG_BLKS)

// ---------------- scratch (no allocations allowed) ----------------
__device__ float    g_deg[NN];
__device__ float    g_dinv[NN];
__device__ float4   g_h1a[NN * 4];   // partial x@W1, k in [0,64)
__device__ float4   g_h1b[NN * 4];   // partial x@W1, k in [64,128)
__device__ uint4    g_h1h[NN * 2];   // scaled h1 as 16 halfs (2x uint4) per node
__device__ uint4    g_acc1h[NN * 2]; // layer-1 aggregate in fp16
__device__ unsigned g_h2h[NN];       // scaled h2 packed as half2
__device__ float2   g_acc2[NN];      // layer-2 aggregate, fp32

union HU { __half2 h; unsigned u; };

// ---------------- kernels ----------------

__global__ void k_init_deg() {
    int i = blockIdx.x * blockDim.x + threadIdx.x;
    if (i < NN) g_deg[i] = 1.0f;  // self-loop
}

// ---- FUSED: blocks [0,782) = gemm1 k-split (each block: 256 nodes x 64 k's);
//      blocks [782,987) = degree REDs. 2x gemm parallelism vs R15 (42 warps/SM).
__global__ void __launch_bounds__(GB) k_fused(const float* __restrict__ x,
                                              const float* __restrict__ W1,
                                              const int* __restrict__ dst) {
    __shared__ __align__(16) float W1s[DF * HID];  // 8 KB
    __shared__ float XS[GB * XP];                  // 33.8 KB
    int tid = threadIdx.x;

    if (blockIdx.x >= 2 * GEMM_BLKS) {
        int b = blockIdx.x - 2 * GEMM_BLKS;
        for (int e = b * GB + tid; e < NE; e += DEG_BLKS * GB)
            atomicAdd(&g_deg[dst[e]], 1.0f);  // RED, no return
        return;
    }

    int kh = (blockIdx.x < GEMM_BLKS) ? 0 : 1;           // k-half
    int bb = (kh == 0) ? blockIdx.x : blockIdx.x - GEMM_BLKS;
    int base = bb * GB;
    int nb = NN - base; if (nb > GB) nb = GB;

    // Only this half's W rows are needed, but loading all 128 is cheap.
    for (int i = tid; i < DF * HID; i += GB) W1s[i] = W1[i];

    float acc[HID];
#pragma unroll
    for (int f = 0; f < HID; f++) acc[f] = 0.0f;

    for (int c2 = 0; c2 < 2; c2++) {
        int ch = kh * 2 + c2;                            // global chunk id 0..3
        __syncthreads();
        for (int i = tid; i < nb * (KC / 4); i += GB) {
            int n = i >> 3, j4 = i & 7;
            float4 v = *(const float4*)(x + (size_t)(base + n) * DF + ch * KC + j4 * 4);
            float* p = &XS[n * XP + j4 * 4];
            p[0] = v.x; p[1] = v.y; p[2] = v.z; p[3] = v.w;
        }
        __syncthreads();

        if (tid < nb) {
            const float* xr = &XS[tid * XP];
#pragma unroll
            for (int kk = 0; kk < KC; kk++) {
                float xs = xr[kk];
                const float4* wr = (const float4*)&W1s[(ch * KC + kk) * HID];
#pragma unroll
                for (int q = 0; q < 4; q++) {
                    float4 w = wr[q];
                    acc[q * 4 + 0] = fmaf(xs, w.x, acc[q * 4 + 0]);
                    acc[q * 4 + 1] = fmaf(xs, w.y, acc[q * 4 + 1]);
                    acc[q * 4 + 2] = fmaf(xs, w.z, acc[q * 4 + 2]);
                    acc[q * 4 + 3] = fmaf(xs, w.w, acc[q * 4 + 3]);
                }
            }
        }
    }

    if (tid >= nb) return;
    int node = base + tid;
    float4* out = (kh == 0) ? &g_h1a[node * 4] : &g_h1b[node * 4];
#pragma unroll
    for (int q = 0; q < 4; q++) {
        float4 v;
        v.x = acc[q * 4 + 0];
        v.y = acc[q * 4 + 1];
        v.z = acc[q * 4 + 2];
        v.w = acc[q * 4 + 3];
        out[q] = v;
    }
}

// dinv = rsqrt(deg); h1 = (a+b)*dinv packed fp16; acc1h init = same (self-loop).
__global__ void k_scale() {
    int i = blockIdx.x * blockDim.x + threadIdx.x;
    if (i >= NN) return;
    float di = rsqrtf(g_deg[i]);  // deg >= 1 always
    g_dinv[i] = di;
#pragma unroll
    for (int q = 0; q < 2; q++) {
        float4 a0 = g_h1a[i * 4 + q * 2 + 0];
        float4 b0 = g_h1b[i * 4 + q * 2 + 0];
        float4 a1 = g_h1a[i * 4 + q * 2 + 1];
        float4 b1 = g_h1b[i * 4 + q * 2 + 1];
        HU p0, p1, p2, p3;
        p0.h = __floats2half2_rn((a0.x + b0.x) * di, (a0.y + b0.y) * di);
        p1.h = __floats2half2_rn((a0.z + b0.z) * di, (a0.w + b0.w) * di);
        p2.h = __floats2half2_rn((a1.x + b1.x) * di, (a1.y + b1.y) * di);
        p3.h = __floats2half2_rn((a1.z + b1.z) * di, (a1.w + b1.w) * di);
        uint4 u = make_uint4(p0.u, p1.u, p2.u, p3.u);
        g_h1h[i * 2 + q] = u;
        g_acc1h[i * 2 + q] = u;   // self-loop init
    }
}

// ---- layer-1 scatter: 2 threads/edge; one uint4 gather + one v4.f16x2 RED ----
__global__ void k_scatter1(const int* __restrict__ src, const int* __restrict__ dst) {
    int t = blockIdx.x * blockDim.x + threadIdx.x;
    if (t >= NE * 2) return;
    int e = t >> 1;
    int c = t & 1;
    int s = src[e];
    int d = dst[e];
    uint4 u = g_h1h[s * 2 + c];
    uint4* p = &g_acc1h[d * 2 + c];
    asm volatile("red.global.add.noftz.v4.f16x2 [%0], {%1, %2, %3, %4};"
                 :: "l"(p), "r"(u.x), "r"(u.y), "r"(u.z), "r"(u.w)
                 : "memory");
}

// Per node: finish layer1 (scale + bias + relu), apply W2, pre-scale for layer2.
__global__ void k_finish1(const float* __restrict__ b1, const float* __restrict__ W2) {
    int i = blockIdx.x * blockDim.x + threadIdx.x;
    if (i >= NN) return;
    float di = g_dinv[i];
    float z0 = 0.0f, z1 = 0.0f;
#pragma unroll
    for (int q = 0; q < 2; q++) {
        uint4 u = g_acc1h[i * 2 + q];
        unsigned uu[4] = {u.x, u.y, u.z, u.w};
#pragma unroll
        for (int j = 0; j < 4; j++) {
            HU p; p.u = uu[j];
            float2 fv = __half22float2(p.h);
            int f = q * 8 + j * 2;
            float v0 = fmaxf(fmaf(di, fv.x, __ldg(&b1[f + 0])), 0.0f);
            float v1 = fmaxf(fmaf(di, fv.y, __ldg(&b1[f + 1])), 0.0f);
            z0 = fmaf(v0, __ldg(&W2[(f + 0) * NC + 0]), z0);
            z1 = fmaf(v0, __ldg(&W2[(f + 0) * NC + 1]), z1);
            z0 = fmaf(v1, __ldg(&W2[(f + 1) * NC + 0]), z0);
            z1 = fmaf(v1, __ldg(&W2[(f + 1) * NC + 1]), z1);
        }
    }
    float2 h;
    h.x = z0 * di;
    h.y = z1 * di;
    g_acc2[i] = h;                    // exact fp32 self-loop term
    HU p; p.h = __floats2half2_rn(h.x, h.y);
    g_h2h[i] = p.u;                   // fp16 scatter payload
}

// ---- layer-2 scatter: fp16 gather (4B), fp32 v2 RED (precision kept) ----
__global__ void k_scatter2(const int* __restrict__ src, const int* __restrict__ dst) {
    int e = blockIdx.x * blockDim.x + threadIdx.x;
    if (e >= NE) return;
    int s = src[e];
    int d = dst[e];
    HU p; p.u = g_h2h[s];
    float2 v = __half22float2(p.h);
    float2* q = &g_acc2[d];
    asm volatile("red.global.add.v2.f32 [%0], {%1, %2};"
                 :: "l"(q), "f"(v.x), "f"(v.y) : "memory");
}

// Finish layer 2 + log_softmax (2 classes).
__global__ void k_final(const float* __restrict__ b2, float* __restrict__ out) {
    int i = blockIdx.x * blockDim.x + threadIdx.x;
    if (i >= NN) return;
    float di = g_dinv[i];
    float2 a = g_acc2[i];
    float z0 = fmaf(di, a.x, __ldg(&b2[0]));
    float z1 = fmaf(di, a.y, __ldg(&b2[1]));
    float m = fmaxf(z0, z1);
    float lse = m + logf(expf(z0 - m) + expf(z1 - m));
    float2 o;
    o.x = z0 - lse;
    o.y = z1 - lse;
    ((float2*)out)[i] = o;
}

// ---------------- launch ----------------

extern "C" void kernel_launch(void* const* d_in, const int* in_sizes, int n_in,
                              void* d_out, int out_size) {
    const float* x = 0; const float* W1 = 0; const float* b1 = 0;
    const float* W2 = 0; const float* b2 = 0; const int* ei = 0;
    for (int i = 0; i < n_in; i++) {
        long long s = in_sizes[i];
        if (s == (long long)NN * DF)      x  = (const float*)d_in[i];
        else if (s == DF * HID)           W1 = (const float*)d_in[i];
        else if (s == HID)                b1 = (const float*)d_in[i];
        else if (s == HID * NC)           W2 = (const float*)d_in[i];
        else if (s == NC)                 b2 = (const float*)d_in[i];
        else if (s == 2LL * NE)           ei = (const int*)d_in[i];
    }
    const int* src = ei;        // row 0
    const int* dst = ei + NE;   // row 1

    const int T = 256;
    const int NBn = (NN + T - 1) / T;
    const int NBe = (NE + T - 1) / T;

    k_init_deg<<<NBn, T>>>();
    k_fused<<<FUSED_BLKS, GB>>>(x, W1, dst);   // gemm1 (k-split) || degree REDs
    k_scale<<<NBn, T>>>();
    k_scatter1<<<(NE * 2 + T - 1) / T, T>>>(src, dst);
    k_finish1<<<NBn, T>>>(b1, W2);
    k_scatter2<<<NBe, T>>>(src, dst);
    k_final<<<NBn, T>>>(b2, (float*)d_out);
}